// round 8
// baseline (speedup 1.0000x reference)
#include <cuda_runtime.h>
#include <cuda_bf16.h>
#include <cstdint>

#define NN   50000
#define MAXE 800000
#define NB   196            // ceil(NN/256)
#define WST  68             // padded stride for W split arrays

// ---------------- scratch (static device globals; no allocation) ----------------
__device__ int      g_deg[NN];          // zero-initialized at load; re-zeroed by scan each call
__device__ int      g_rowptr[NN + 1];
__device__ int      g_cursor[NN];
__device__ int      g_esrc[MAXE];
__device__ unsigned g_bstate[NB];       // lookback state: [31:30]=flag (1=agg,2=prefix), [29:0]=sum
__device__ float    g_dsinv[NN];
__device__ float    g_feat[NN * 64];    // g = (h @ W) * dsinv[row]
__device__ float    g_hbuf[NN * 64];    // layer output ping buffer
__device__ float    g_Wh[3 * 64 * WST]; // per-layer W tf32-hi, [n][packed k] stride WST
__device__ float    g_Wl[3 * 64 * WST]; // per-layer W tf32-lo

// per-block dtype consensus: read first 256 int64 slots (in-bounds for BOTH layouts)
__device__ __forceinline__ int block_detect_i64(const void* ei) {
    long long v = ((const long long*)ei)[threadIdx.x & 255];
    return __syncthreads_and(v >= 0 && v < NN);
}

__device__ __forceinline__ unsigned f2tf32(float a) {
    unsigned r;
    asm("cvt.rna.tf32.f32 %0, %1;" : "=r"(r) : "f"(a));
    return r;
}

// ---------------- W split precompute: 3 blocks, one per layer ----------------
// packed slot within each kstep-octet: k = ks*8 + tg + 4*h  ->  slot = ks*8 + tg*2 + h
// so (b0,b1) = (W^T[n][k0+tg], W^T[n][k0+tg+4]) sit adjacent -> one LDS.64 in gemm.
__global__ __launch_bounds__(256) void wsplit_kernel(const float* __restrict__ W0,
                                                     const float* __restrict__ W1,
                                                     const float* __restrict__ W2) {
    const float* W = (blockIdx.x == 0) ? W0 : (blockIdx.x == 1) ? W1 : W2;
    float* dh = g_Wh + blockIdx.x * 64 * WST;
    float* dl = g_Wl + blockIdx.x * 64 * WST;
    for (int e = threadIdx.x; e < 4096; e += 256) {
        int k = e >> 6, n = e & 63;          // W is [k][n] row-major
        float w = W[e];
        unsigned hi = f2tf32(w);
        float lof = w - __uint_as_float(hi);
        int ks = k >> 3, r = k & 7;
        int slot = ks * 8 + (r & 3) * 2 + (r >> 2);
        dh[n * WST + slot] = __uint_as_float(hi);
        dl[n * WST + slot] = __uint_as_float(f2tf32(lof));
    }
}

// ---------------- hist: deg histogram (+ lookback-state reset by block 0) ----------------
__global__ __launch_bounds__(256) void hist_kernel(const void* __restrict__ ei, int E) {
    int is64 = block_detect_i64(ei);
    if (blockIdx.x == 0 && threadIdx.x < NB) g_bstate[threadIdx.x] = 0u;
    int e = blockIdx.x * 256 + threadIdx.x;
    if (e < E) {
        int d = is64 ? (int)((const long long*)ei)[(long long)E + e]
                     : ((const int*)ei)[(long long)E + e];
        if ((unsigned)d < (unsigned)NN) atomicAdd(&g_deg[d], 1);
    }
}

// ---------------- single-kernel decoupled-lookback scan ----------------
__global__ __launch_bounds__(256) void scan_kernel() {
    const unsigned full = 0xffffffffu;
    __shared__ int sh[8];
    __shared__ int s_prefix;
    int b = blockIdx.x, t = threadIdx.x;
    int lane = t & 31, wid = t >> 5;
    int i = b * 256 + t;

    int v = (i < NN) ? g_deg[i] : 0;

    int x = v;
#pragma unroll
    for (int d = 1; d < 32; d <<= 1) {
        int n = __shfl_up_sync(full, x, d);
        if (lane >= d) x += n;
    }
    if (lane == 31) sh[wid] = x;
    __syncthreads();
    if (wid == 0) {
        int w = (lane < 8) ? sh[lane] : 0;
#pragma unroll
        for (int d = 1; d < 8; d <<= 1) {
            int n = __shfl_up_sync(full, w, d);
            if (lane >= d) w += n;
        }
        if (lane < 8) sh[lane] = w;
    }
    __syncthreads();
    int incl = x + (wid ? sh[wid - 1] : 0);
    int S = sh[7];

    if (t == 0 && b > 0) atomicExch((int*)&g_bstate[b], (1 << 30) | S);

    if (wid == 0) {
        int running = 0;
        if (b > 0) {
            int idx = b - 1;
            while (true) {
                int j = idx - lane;
                unsigned st;
                do {
                    st = (j >= 0) ? (unsigned)atomicAdd((int*)&g_bstate[j], 0)
                                  : (2u << 30);
                } while (__any_sync(full, (st >> 30) == 0));
                int val = (int)(st & 0x3FFFFFFF);
                unsigned pm = __ballot_sync(full, (st >> 30) == 2u);
                if (pm) {
                    int firstP = __ffs(pm) - 1;
                    int contrib = (lane <= firstP) ? val : 0;
#pragma unroll
                    for (int d = 16; d; d >>= 1) contrib += __shfl_down_sync(full, contrib, d);
                    running += __shfl_sync(full, contrib, 0);
                    break;
                } else {
                    int contrib = val;
#pragma unroll
                    for (int d = 16; d; d >>= 1) contrib += __shfl_down_sync(full, contrib, d);
                    running += __shfl_sync(full, contrib, 0);
                    idx -= 32;
                }
            }
        }
        if (lane == 0) {
            atomicExch((int*)&g_bstate[b], (2 << 30) | (running + S));
            s_prefix = running;
        }
    }
    __syncthreads();

    if (i < NN) {
        int excl = s_prefix + incl - v;
        g_rowptr[i] = excl;
        g_cursor[i] = excl;
        g_dsinv[i]  = rsqrtf((float)(v + 1));
        g_deg[i]    = 0;
        if (i == NN - 1) g_rowptr[NN] = s_prefix + incl;
    }
}

// ---------------- scatter: fill CSR adjacency ----------------
__global__ __launch_bounds__(256) void scatter_kernel(const void* __restrict__ ei, int E) {
    int is64 = block_detect_i64(ei);
    int e = blockIdx.x * 256 + threadIdx.x;
    if (e < E) {
        int s, d;
        if (is64) {
            s = (int)((const long long*)ei)[e];
            d = (int)((const long long*)ei)[(long long)E + e];
        } else {
            s = ((const int*)ei)[e];
            d = ((const int*)ei)[(long long)E + e];
        }
        if ((unsigned)d < (unsigned)NN && (unsigned)s < (unsigned)NN) {
            int p = atomicAdd(&g_cursor[d], 1);
            if ((unsigned)p < (unsigned)MAXE) g_esrc[p] = s;
        }
    }
}

// ---------------- tensor-core GEMM: g = (A @ W) * dsinv[row] ----------------
// 256 thr / 8 warps; each warp: 16 rows x 64 cols. A straight from gmem (sector-
// aligned fragments), W hi/lo from smem (packed pairs -> LDS.64, conflict-free).
// C = Ah*Wh + Ah*Wl + Al*Wh  (lo*lo dropped; rel err ~1e-6)
__device__ __forceinline__ void mma_tf32(float* c, unsigned a0, unsigned a1,
                                         unsigned a2, unsigned a3,
                                         unsigned b0, unsigned b1) {
    asm volatile(
        "mma.sync.aligned.m16n8k8.row.col.f32.tf32.tf32.f32 "
        "{%0,%1,%2,%3}, {%4,%5,%6,%7}, {%8,%9}, {%0,%1,%2,%3};"
        : "+f"(c[0]), "+f"(c[1]), "+f"(c[2]), "+f"(c[3])
        : "r"(a0), "r"(a1), "r"(a2), "r"(a3), "r"(b0), "r"(b1));
}

__global__ __launch_bounds__(256, 4) void gemm_mma_kernel(const float* __restrict__ Ain,
                                                          int layer, int use_hbuf) {
    __shared__ float sWh[64 * WST];
    __shared__ float sWl[64 * WST];
    const float* A = use_hbuf ? g_hbuf : Ain;

    int t = threadIdx.x;
    {   // copy precomputed W split: 2 x 1088 float4
        const float4* srch = (const float4*)(g_Wh + layer * 64 * WST);
        const float4* srcl = (const float4*)(g_Wl + layer * 64 * WST);
        float4* dh = (float4*)sWh;
        float4* dl = (float4*)sWl;
        for (int i = t; i < (64 * WST) / 4; i += 256) { dh[i] = srch[i]; dl[i] = srcl[i]; }
    }
    __syncthreads();

    int warp = t >> 5, lane = t & 31;
    int g = lane >> 2, tg = lane & 3;
    int r0 = blockIdx.x * 128 + warp * 16 + g;     // rows r0, r0+8
    int r1 = r0 + 8;
    int ar0 = min(r0, NN - 1), ar1 = min(r1, NN - 1);
    const float* Ar0 = A + (size_t)ar0 * 64;
    const float* Ar1 = A + (size_t)ar1 * 64;

    float acc[8][4];
#pragma unroll
    for (int j = 0; j < 8; j++)
#pragma unroll
        for (int c = 0; c < 4; c++) acc[j][c] = 0.f;

#pragma unroll
    for (int ks = 0; ks < 8; ks++) {
        int k0 = ks * 8;
        float a0 = Ar0[k0 + tg];
        float a1 = Ar1[k0 + tg];
        float a2 = Ar0[k0 + tg + 4];
        float a3 = Ar1[k0 + tg + 4];
        unsigned ah0 = f2tf32(a0), ah1 = f2tf32(a1), ah2 = f2tf32(a2), ah3 = f2tf32(a3);
        unsigned al0 = f2tf32(a0 - __uint_as_float(ah0));
        unsigned al1 = f2tf32(a1 - __uint_as_float(ah1));
        unsigned al2 = f2tf32(a2 - __uint_as_float(ah2));
        unsigned al3 = f2tf32(a3 - __uint_as_float(ah3));
#pragma unroll
        for (int j = 0; j < 8; j++) {
            int cbase = (8 * j + g) * WST + k0 + tg * 2;   // packed pair offset
            float2 bh = *(const float2*)&sWh[cbase];
            float2 bl = *(const float2*)&sWl[cbase];
            unsigned bh0 = __float_as_uint(bh.x), bh1 = __float_as_uint(bh.y);
            unsigned bl0 = __float_as_uint(bl.x), bl1 = __float_as_uint(bl.y);
            mma_tf32(acc[j], ah0, ah1, ah2, ah3, bh0, bh1);
            mma_tf32(acc[j], ah0, ah1, ah2, ah3, bl0, bl1);
            mma_tf32(acc[j], al0, al1, al2, al3, bh0, bh1);
        }
    }

    float s0 = (r0 < NN) ? g_dsinv[r0] : 0.f;
    float s1 = (r1 < NN) ? g_dsinv[r1] : 0.f;
#pragma unroll
    for (int j = 0; j < 8; j++) {
        int col = 8 * j + 2 * tg;
        if (r0 < NN)
            *(float2*)(g_feat + (size_t)r0 * 64 + col) =
                make_float2(acc[j][0] * s0, acc[j][1] * s0);
        if (r1 < NN)
            *(float2*)(g_feat + (size_t)r1 * 64 + col) =
                make_float2(acc[j][2] * s1, acc[j][3] * s1);
    }
}

// ---------------- aggregation: one warp per node, CSR gather, 8-deep MLP ----------------
__global__ __launch_bounds__(256) void aggregate_kernel(const float* __restrict__ bias,
                                                        float* __restrict__ dout,
                                                        int mode) {
    int warp = (blockIdx.x * blockDim.x + threadIdx.x) >> 5;
    int lane = threadIdx.x & 31;
    if (warp >= NN) return;
    int node = warp;
    int beg = g_rowptr[node];
    int end = g_rowptr[node + 1];

    const float2* __restrict__ Gv = (const float2*)g_feat;
    int off = node * 32 + lane;
    float2 s0v = Gv[off];
    float ax = s0v.x, ay = s0v.y;

    const unsigned full = 0xffffffffu;
    for (int base = beg; base < end; base += 32) {
        int idx = base + lane;
        int mysrc = (idx < end) ? g_esrc[idx] : 0;
        int cnt = min(32, end - base);
        int i = 0;
        for (; i + 8 <= cnt; i += 8) {
            int s0 = __shfl_sync(full, mysrc, i);
            int s1 = __shfl_sync(full, mysrc, i + 1);
            int s2 = __shfl_sync(full, mysrc, i + 2);
            int s3 = __shfl_sync(full, mysrc, i + 3);
            int s4 = __shfl_sync(full, mysrc, i + 4);
            int s5 = __shfl_sync(full, mysrc, i + 5);
            int s6 = __shfl_sync(full, mysrc, i + 6);
            int s7 = __shfl_sync(full, mysrc, i + 7);
            float2 v0 = Gv[s0 * 32 + lane];
            float2 v1 = Gv[s1 * 32 + lane];
            float2 v2 = Gv[s2 * 32 + lane];
            float2 v3 = Gv[s3 * 32 + lane];
            float2 v4 = Gv[s4 * 32 + lane];
            float2 v5 = Gv[s5 * 32 + lane];
            float2 v6 = Gv[s6 * 32 + lane];
            float2 v7 = Gv[s7 * 32 + lane];
            ax += v0.x; ay += v0.y; ax += v1.x; ay += v1.y;
            ax += v2.x; ay += v2.y; ax += v3.x; ay += v3.y;
            ax += v4.x; ay += v4.y; ax += v5.x; ay += v5.y;
            ax += v6.x; ay += v6.y; ax += v7.x; ay += v7.y;
        }
        for (; i < cnt; i++) {
            int s = __shfl_sync(full, mysrc, i);
            float2 v = Gv[s * 32 + lane];
            ax += v.x; ay += v.y;
        }
    }

    float ds = g_dsinv[node];
    float o0 = fmaf(ds, ax, bias[lane * 2]);
    float o1 = fmaf(ds, ay, bias[lane * 2 + 1]);
    float2* outv;
    if (mode < 2) {
        o0 = fmaxf(o0, 0.f);
        o1 = fmaxf(o1, 0.f);
        outv = (float2*)g_hbuf;
    } else {
        outv = (float2*)dout;
    }
    outv[off] = make_float2(o0, o1);
}

// ---------------- launch ----------------
extern "C" void kernel_launch(void* const* d_in, const int* in_sizes, int n_in,
                              void* d_out, int out_size) {
    const float* x  = (const float*)d_in[0];
    const void*  ei = d_in[1];
    const float* W0 = (const float*)d_in[2];
    const float* b0 = (const float*)d_in[3];
    const float* W1 = (const float*)d_in[4];
    const float* b1 = (const float*)d_in[5];
    const float* W2 = (const float*)d_in[6];
    const float* b2 = (const float*)d_in[7];
    float* out = (float*)d_out;

    int E = in_sizes[1] / 2;

    int gemm_blocks = (NN + 127) / 128;
    int agg_blocks  = (NN * 32 + 255) / 256;

    wsplit_kernel<<<3, 256>>>(W0, W1, W2);                 // 1
    hist_kernel<<<(E + 255) / 256, 256>>>(ei, E);          // 2
    scan_kernel<<<NB, 256>>>();                            // 3
    gemm_mma_kernel<<<gemm_blocks, 256>>>(x, 0, 0);        // 4 -> profiled
    scatter_kernel<<<(E + 255) / 256, 256>>>(ei, E);       // 5
    aggregate_kernel<<<agg_blocks, 256>>>(b0, out, 0);     // 6
    gemm_mma_kernel<<<gemm_blocks, 256>>>(x, 1, 1);
    aggregate_kernel<<<agg_blocks, 256>>>(b1, out, 1);
    gemm_mma_kernel<<<gemm_blocks, 256>>>(x, 2, 1);
    aggregate_kernel<<<agg_blocks, 256>>>(b2, out, 2);
}

// round 10
// speedup vs baseline: 1.3938x; 1.3938x over previous
#include <cuda_runtime.h>
#include <cuda_bf16.h>
#include <cstdint>

#define NN   50000
#define MAXE 800000
#define NB   196            // ceil(NN/256)
#define WST  68             // padded stride for W split arrays

// ---------------- scratch (static device globals; no allocation) ----------------
__device__ int      g_deg[NN];          // zero-initialized at load; re-zeroed by scan each call
__device__ int      g_rowptr[NN + 1];
__device__ int      g_cursor[NN];
__device__ int      g_esrc[MAXE];
__device__ unsigned g_bstate[NB];       // lookback state: [31:30]=flag (1=agg,2=prefix), [29:0]=sum
__device__ float    g_dsinv[NN];
__device__ float    g_feat[NN * 64];    // g = (h @ W) * dsinv[row]
__device__ float    g_hbuf[NN * 64];    // layer output ping buffer
__device__ float    g_Wh[3 * 64 * WST]; // per-layer W tf32-hi, [n][packed k] stride WST
__device__ float    g_Wl[3 * 64 * WST]; // per-layer W tf32-lo

// per-block dtype consensus: read first 256 int64 slots (in-bounds for BOTH layouts)
__device__ __forceinline__ int block_detect_i64(const void* ei) {
    long long v = ((const long long*)ei)[threadIdx.x & 255];
    return __syncthreads_and(v >= 0 && v < NN);
}

__device__ __forceinline__ unsigned f2tf32(float a) {
    unsigned r;
    asm("cvt.rna.tf32.f32 %0, %1;" : "=r"(r) : "f"(a));
    return r;
}

// ---------------- W split precompute: 3 blocks, one per layer ----------------
// packed slot: k = ks*8 + tg + 4*h  ->  slot = ks*8 + tg*2 + h
// so (b0,b1) = (W^T[n][k0+tg], W^T[n][k0+tg+4]) sit adjacent -> one 8B load.
__global__ __launch_bounds__(256) void wsplit_kernel(const float* __restrict__ W0,
                                                     const float* __restrict__ W1,
                                                     const float* __restrict__ W2) {
    const float* W = (blockIdx.x == 0) ? W0 : (blockIdx.x == 1) ? W1 : W2;
    float* dh = g_Wh + blockIdx.x * 64 * WST;
    float* dl = g_Wl + blockIdx.x * 64 * WST;
    for (int e = threadIdx.x; e < 4096; e += 256) {
        int k = e >> 6, n = e & 63;          // W is [k][n] row-major
        float w = W[e];
        unsigned hi = f2tf32(w);
        float lof = w - __uint_as_float(hi);
        int ks = k >> 3, r = k & 7;
        int slot = ks * 8 + (r & 3) * 2 + (r >> 2);
        dh[n * WST + slot] = __uint_as_float(hi);
        dl[n * WST + slot] = __uint_as_float(f2tf32(lof));
    }
}

// ---------------- hist: deg histogram (+ lookback-state reset by block 0) ----------------
__global__ __launch_bounds__(256) void hist_kernel(const void* __restrict__ ei, int E) {
    int is64 = block_detect_i64(ei);
    if (blockIdx.x == 0 && threadIdx.x < NB) g_bstate[threadIdx.x] = 0u;
    int e = blockIdx.x * 256 + threadIdx.x;
    if (e < E) {
        int d = is64 ? (int)((const long long*)ei)[(long long)E + e]
                     : ((const int*)ei)[(long long)E + e];
        if ((unsigned)d < (unsigned)NN) atomicAdd(&g_deg[d], 1);
    }
}

// ---------------- single-kernel decoupled-lookback scan ----------------
__global__ __launch_bounds__(256) void scan_kernel() {
    const unsigned full = 0xffffffffu;
    __shared__ int sh[8];
    __shared__ int s_prefix;
    int b = blockIdx.x, t = threadIdx.x;
    int lane = t & 31, wid = t >> 5;
    int i = b * 256 + t;

    int v = (i < NN) ? g_deg[i] : 0;

    int x = v;
#pragma unroll
    for (int d = 1; d < 32; d <<= 1) {
        int n = __shfl_up_sync(full, x, d);
        if (lane >= d) x += n;
    }
    if (lane == 31) sh[wid] = x;
    __syncthreads();
    if (wid == 0) {
        int w = (lane < 8) ? sh[lane] : 0;
#pragma unroll
        for (int d = 1; d < 8; d <<= 1) {
            int n = __shfl_up_sync(full, w, d);
            if (lane >= d) w += n;
        }
        if (lane < 8) sh[lane] = w;
    }
    __syncthreads();
    int incl = x + (wid ? sh[wid - 1] : 0);
    int S = sh[7];

    if (t == 0 && b > 0) atomicExch((int*)&g_bstate[b], (1 << 30) | S);

    if (wid == 0) {
        int running = 0;
        if (b > 0) {
            int idx = b - 1;
            while (true) {
                int j = idx - lane;
                unsigned st;
                do {
                    st = (j >= 0) ? (unsigned)atomicAdd((int*)&g_bstate[j], 0)
                                  : (2u << 30);
                } while (__any_sync(full, (st >> 30) == 0));
                int val = (int)(st & 0x3FFFFFFF);
                unsigned pm = __ballot_sync(full, (st >> 30) == 2u);
                if (pm) {
                    int firstP = __ffs(pm) - 1;
                    int contrib = (lane <= firstP) ? val : 0;
#pragma unroll
                    for (int d = 16; d; d >>= 1) contrib += __shfl_down_sync(full, contrib, d);
                    running += __shfl_sync(full, contrib, 0);
                    break;
                } else {
                    int contrib = val;
#pragma unroll
                    for (int d = 16; d; d >>= 1) contrib += __shfl_down_sync(full, contrib, d);
                    running += __shfl_sync(full, contrib, 0);
                    idx -= 32;
                }
            }
        }
        if (lane == 0) {
            atomicExch((int*)&g_bstate[b], (2 << 30) | (running + S));
            s_prefix = running;
        }
    }
    __syncthreads();

    if (i < NN) {
        int excl = s_prefix + incl - v;
        g_rowptr[i] = excl;
        g_cursor[i] = excl;
        g_dsinv[i]  = rsqrtf((float)(v + 1));
        g_deg[i]    = 0;
        if (i == NN - 1) g_rowptr[NN] = s_prefix + incl;
    }
}

// ---------------- scatter: fill CSR adjacency ----------------
__global__ __launch_bounds__(256) void scatter_kernel(const void* __restrict__ ei, int E) {
    int is64 = block_detect_i64(ei);
    int e = blockIdx.x * 256 + threadIdx.x;
    if (e < E) {
        int s, d;
        if (is64) {
            s = (int)((const long long*)ei)[e];
            d = (int)((const long long*)ei)[(long long)E + e];
        } else {
            s = ((const int*)ei)[e];
            d = ((const int*)ei)[(long long)E + e];
        }
        if ((unsigned)d < (unsigned)NN && (unsigned)s < (unsigned)NN) {
            int p = atomicAdd(&g_cursor[d], 1);
            if ((unsigned)p < (unsigned)MAXE) g_esrc[p] = s;
        }
    }
}

// ---------------- tensor-core GEMM: g = (A @ W) * dsinv[row] ----------------
// 256 thr / 8 warps; block tile 64 rows x 64 cols. Warp w owns ntile w (cols 8w..8w+7)
// and iterates 4 mtiles of 16 rows. B (hi/lo) lives in 32 registers per lane, loaded
// once from precomputed packed global. A staged via float4 -> smem (stride 68,
// conflict-free: bank = (4g+tg+c) mod 32 covers all 32).
// C = Ah*Wh + Ah*Wl + Al*Wh  (lo*lo dropped; rel err ~1e-6)
__device__ __forceinline__ void mma_tf32(float* c, unsigned a0, unsigned a1,
                                         unsigned a2, unsigned a3,
                                         unsigned b0, unsigned b1) {
    asm volatile(
        "mma.sync.aligned.m16n8k8.row.col.f32.tf32.tf32.f32 "
        "{%0,%1,%2,%3}, {%4,%5,%6,%7}, {%8,%9}, {%0,%1,%2,%3};"
        : "+f"(c[0]), "+f"(c[1]), "+f"(c[2]), "+f"(c[3])
        : "r"(a0), "r"(a1), "r"(a2), "r"(a3), "r"(b0), "r"(b1));
}

__global__ __launch_bounds__(256) void gemm_mma_kernel(const float* __restrict__ Ain,
                                                       int layer, int use_hbuf) {
    __shared__ float sA[64 * 68];
    const float* A = use_hbuf ? g_hbuf : Ain;

    int t = threadIdx.x;
    int warp = t >> 5, lane = t & 31;
    int g = lane >> 2, tg = lane & 3;
    int row0 = blockIdx.x * 64;

    // B fragments for this warp's ntile: issue loads first (overlap with A fill)
    const float* Whp = g_Wh + layer * 64 * WST + (8 * warp + g) * WST + tg * 2;
    const float* Wlp = g_Wl + layer * 64 * WST + (8 * warp + g) * WST + tg * 2;
    float2 bhf[8], blf[8];
#pragma unroll
    for (int ks = 0; ks < 8; ks++) {
        bhf[ks] = *(const float2*)(Whp + ks * 8);
        blf[ks] = *(const float2*)(Wlp + ks * 8);
    }

    // A tile -> smem: 64 rows x 64 cols (stride 68)
#pragma unroll
    for (int i = 0; i < 4; i++) {
        int q = t + i * 256;           // float4 index 0..1023
        int r = q >> 4;
        int c4 = (q & 15) << 2;
        float4 v = make_float4(0.f, 0.f, 0.f, 0.f);
        int grow = row0 + r;
        if (grow < NN) v = *(const float4*)(A + (size_t)grow * 64 + c4);
        *(float4*)(sA + r * 68 + c4) = v;
    }
    __syncthreads();

    float acc[4][4];
#pragma unroll
    for (int m = 0; m < 4; m++)
#pragma unroll
        for (int c = 0; c < 4; c++) acc[m][c] = 0.f;

#pragma unroll
    for (int mt = 0; mt < 4; mt++) {
#pragma unroll
        for (int ks = 0; ks < 8; ks++) {
            int base = (mt * 16 + g) * 68 + ks * 8 + tg;
            float a0 = sA[base];
            float a1 = sA[base + 8 * 68];
            float a2 = sA[base + 4];
            float a3 = sA[base + 8 * 68 + 4];
            unsigned ah0 = f2tf32(a0), ah1 = f2tf32(a1);
            unsigned ah2 = f2tf32(a2), ah3 = f2tf32(a3);
            unsigned al0 = f2tf32(a0 - __uint_as_float(ah0));
            unsigned al1 = f2tf32(a1 - __uint_as_float(ah1));
            unsigned al2 = f2tf32(a2 - __uint_as_float(ah2));
            unsigned al3 = f2tf32(a3 - __uint_as_float(ah3));
            unsigned bh0 = __float_as_uint(bhf[ks].x), bh1 = __float_as_uint(bhf[ks].y);
            unsigned bl0 = __float_as_uint(blf[ks].x), bl1 = __float_as_uint(blf[ks].y);
            mma_tf32(acc[mt], ah0, ah1, ah2, ah3, bh0, bh1);
            mma_tf32(acc[mt], ah0, ah1, ah2, ah3, bl0, bl1);
            mma_tf32(acc[mt], al0, al1, al2, al3, bh0, bh1);
        }
    }

    // epilogue: scale by dsinv[row]; warp's cols are 8*warp + 2*tg
#pragma unroll
    for (int mt = 0; mt < 4; mt++) {
        int r0 = row0 + mt * 16 + g;
        int r1 = r0 + 8;
        int col = 8 * warp + 2 * tg;
        if (r0 < NN) {
            float s0 = g_dsinv[r0];
            *(float2*)(g_feat + (size_t)r0 * 64 + col) =
                make_float2(acc[mt][0] * s0, acc[mt][1] * s0);
        }
        if (r1 < NN) {
            float s1 = g_dsinv[r1];
            *(float2*)(g_feat + (size_t)r1 * 64 + col) =
                make_float2(acc[mt][2] * s1, acc[mt][3] * s1);
        }
    }
}

// ---------------- aggregation: one warp per node, CSR gather, 8-deep MLP ----------------
__global__ __launch_bounds__(256) void aggregate_kernel(const float* __restrict__ bias,
                                                        float* __restrict__ dout,
                                                        int mode) {
    int warp = (blockIdx.x * blockDim.x + threadIdx.x) >> 5;
    int lane = threadIdx.x & 31;
    if (warp >= NN) return;
    int node = warp;
    int beg = g_rowptr[node];
    int end = g_rowptr[node + 1];

    const float2* __restrict__ Gv = (const float2*)g_feat;
    int off = node * 32 + lane;
    float2 s0v = Gv[off];
    float ax = s0v.x, ay = s0v.y;

    const unsigned full = 0xffffffffu;
    for (int base = beg; base < end; base += 32) {
        int idx = base + lane;
        int mysrc = (idx < end) ? g_esrc[idx] : 0;
        int cnt = min(32, end - base);
        int i = 0;
        for (; i + 8 <= cnt; i += 8) {
            int s0 = __shfl_sync(full, mysrc, i);
            int s1 = __shfl_sync(full, mysrc, i + 1);
            int s2 = __shfl_sync(full, mysrc, i + 2);
            int s3 = __shfl_sync(full, mysrc, i + 3);
            int s4 = __shfl_sync(full, mysrc, i + 4);
            int s5 = __shfl_sync(full, mysrc, i + 5);
            int s6 = __shfl_sync(full, mysrc, i + 6);
            int s7 = __shfl_sync(full, mysrc, i + 7);
            float2 v0 = Gv[s0 * 32 + lane];
            float2 v1 = Gv[s1 * 32 + lane];
            float2 v2 = Gv[s2 * 32 + lane];
            float2 v3 = Gv[s3 * 32 + lane];
            float2 v4 = Gv[s4 * 32 + lane];
            float2 v5 = Gv[s5 * 32 + lane];
            float2 v6 = Gv[s6 * 32 + lane];
            float2 v7 = Gv[s7 * 32 + lane];
            ax += v0.x; ay += v0.y; ax += v1.x; ay += v1.y;
            ax += v2.x; ay += v2.y; ax += v3.x; ay += v3.y;
            ax += v4.x; ay += v4.y; ax += v5.x; ay += v5.y;
            ax += v6.x; ay += v6.y; ax += v7.x; ay += v7.y;
        }
        for (; i < cnt; i++) {
            int s = __shfl_sync(full, mysrc, i);
            float2 v = Gv[s * 32 + lane];
            ax += v.x; ay += v.y;
        }
    }

    float ds = g_dsinv[node];
    float o0 = fmaf(ds, ax, bias[lane * 2]);
    float o1 = fmaf(ds, ay, bias[lane * 2 + 1]);
    float2* outv;
    if (mode < 2) {
        o0 = fmaxf(o0, 0.f);
        o1 = fmaxf(o1, 0.f);
        outv = (float2*)g_hbuf;
    } else {
        outv = (float2*)dout;
    }
    outv[off] = make_float2(o0, o1);
}

// ---------------- launch ----------------
extern "C" void kernel_launch(void* const* d_in, const int* in_sizes, int n_in,
                              void* d_out, int out_size) {
    const float* x  = (const float*)d_in[0];
    const void*  ei = d_in[1];
    const float* W0 = (const float*)d_in[2];
    const float* b0 = (const float*)d_in[3];
    const float* W1 = (const float*)d_in[4];
    const float* b1 = (const float*)d_in[5];
    const float* W2 = (const float*)d_in[6];
    const float* b2 = (const float*)d_in[7];
    float* out = (float*)d_out;

    int E = in_sizes[1] / 2;

    int gemm_blocks = (NN + 63) / 64;
    int agg_blocks  = (NN * 32 + 255) / 256;

    wsplit_kernel<<<3, 256>>>(W0, W1, W2);                 // 1
    hist_kernel<<<(E + 255) / 256, 256>>>(ei, E);          // 2
    scan_kernel<<<NB, 256>>>();                            // 3
    gemm_mma_kernel<<<gemm_blocks, 256>>>(x, 0, 0);        // 4 -> profiled
    scatter_kernel<<<(E + 255) / 256, 256>>>(ei, E);       // 5
    aggregate_kernel<<<agg_blocks, 256>>>(b0, out, 0);     // 6
    gemm_mma_kernel<<<gemm_blocks, 256>>>(x, 1, 1);
    aggregate_kernel<<<agg_blocks, 256>>>(b1, out, 1);
    gemm_mma_kernel<<<gemm_blocks, 256>>>(x, 2, 1);
    aggregate_kernel<<<agg_blocks, 256>>>(b2, out, 2);
}

// round 11
// speedup vs baseline: 1.6164x; 1.1597x over previous
#include <cuda_runtime.h>
#include <cuda_fp16.h>
#include <cstdint>

#define NN   50000
#define MAXE 800000
#define NB   196            // ceil(NN/256)

// ---------------- scratch (static device globals; no allocation) ----------------
__device__ int      g_deg[NN];          // zero-initialized at load; re-zeroed by scan each call
__device__ int      g_rowptr[NN + 1];
__device__ int      g_cursor[NN];
__device__ int      g_esrc[MAXE];
__device__ unsigned g_bstate[NB];       // lookback state: [31:30]=flag (1=agg,2=prefix), [29:0]=sum
__device__ float    g_dsinv[NN];
__device__ __half   g_feat[NN * 64];    // g = (h @ W) * dsinv[row], fp16 for gather bandwidth
__device__ float    g_hbuf[NN * 64];    // layer output ping buffer (fp32)

// per-block dtype consensus: read first 256 int64 slots (in-bounds for BOTH layouts)
__device__ __forceinline__ int block_detect_i64(const void* ei) {
    long long v = ((const long long*)ei)[threadIdx.x & 255];
    return __syncthreads_and(v >= 0 && v < NN);
}

// ---------------- hist: deg histogram (+ lookback-state reset by block 0) ----------------
__global__ __launch_bounds__(256) void hist_kernel(const void* __restrict__ ei, int E) {
    int is64 = block_detect_i64(ei);
    if (blockIdx.x == 0 && threadIdx.x < NB) g_bstate[threadIdx.x] = 0u;
    int e = blockIdx.x * 256 + threadIdx.x;
    if (e < E) {
        int d = is64 ? (int)((const long long*)ei)[(long long)E + e]
                     : ((const int*)ei)[(long long)E + e];
        if ((unsigned)d < (unsigned)NN) atomicAdd(&g_deg[d], 1);
    }
}

// ---------------- single-kernel decoupled-lookback scan ----------------
__global__ __launch_bounds__(256) void scan_kernel() {
    const unsigned full = 0xffffffffu;
    __shared__ int sh[8];
    __shared__ int s_prefix;
    int b = blockIdx.x, t = threadIdx.x;
    int lane = t & 31, wid = t >> 5;
    int i = b * 256 + t;

    int v = (i < NN) ? g_deg[i] : 0;

    int x = v;
#pragma unroll
    for (int d = 1; d < 32; d <<= 1) {
        int n = __shfl_up_sync(full, x, d);
        if (lane >= d) x += n;
    }
    if (lane == 31) sh[wid] = x;
    __syncthreads();
    if (wid == 0) {
        int w = (lane < 8) ? sh[lane] : 0;
#pragma unroll
        for (int d = 1; d < 8; d <<= 1) {
            int n = __shfl_up_sync(full, w, d);
            if (lane >= d) w += n;
        }
        if (lane < 8) sh[lane] = w;
    }
    __syncthreads();
    int incl = x + (wid ? sh[wid - 1] : 0);
    int S = sh[7];

    if (t == 0 && b > 0) atomicExch((int*)&g_bstate[b], (1 << 30) | S);

    if (wid == 0) {
        int running = 0;
        if (b > 0) {
            int idx = b - 1;
            while (true) {
                int j = idx - lane;
                unsigned st;
                do {
                    st = (j >= 0) ? (unsigned)atomicAdd((int*)&g_bstate[j], 0)
                                  : (2u << 30);
                } while (__any_sync(full, (st >> 30) == 0));
                int val = (int)(st & 0x3FFFFFFF);
                unsigned pm = __ballot_sync(full, (st >> 30) == 2u);
                if (pm) {
                    int firstP = __ffs(pm) - 1;
                    int contrib = (lane <= firstP) ? val : 0;
#pragma unroll
                    for (int d = 16; d; d >>= 1) contrib += __shfl_down_sync(full, contrib, d);
                    running += __shfl_sync(full, contrib, 0);
                    break;
                } else {
                    int contrib = val;
#pragma unroll
                    for (int d = 16; d; d >>= 1) contrib += __shfl_down_sync(full, contrib, d);
                    running += __shfl_sync(full, contrib, 0);
                    idx -= 32;
                }
            }
        }
        if (lane == 0) {
            atomicExch((int*)&g_bstate[b], (2 << 30) | (running + S));
            s_prefix = running;
        }
    }
    __syncthreads();

    if (i < NN) {
        int excl = s_prefix + incl - v;
        g_rowptr[i] = excl;
        g_cursor[i] = excl;
        g_dsinv[i]  = rsqrtf((float)(v + 1));
        g_deg[i]    = 0;
        if (i == NN - 1) g_rowptr[NN] = s_prefix + incl;
    }
}

// ---------------- scatter: fill CSR adjacency ----------------
__global__ __launch_bounds__(256) void scatter_kernel(const void* __restrict__ ei, int E) {
    int is64 = block_detect_i64(ei);
    int e = blockIdx.x * 256 + threadIdx.x;
    if (e < E) {
        int s, d;
        if (is64) {
            s = (int)((const long long*)ei)[e];
            d = (int)((const long long*)ei)[(long long)E + e];
        } else {
            s = ((const int*)ei)[e];
            d = ((const int*)ei)[(long long)E + e];
        }
        if ((unsigned)d < (unsigned)NN && (unsigned)s < (unsigned)NN) {
            int p = atomicAdd(&g_cursor[d], 1);
            if ((unsigned)p < (unsigned)MAXE) g_esrc[p] = s;
        }
    }
}

// ---------------- tensor-core GEMM (R7 config): g = (A @ W) * dsinv, fp16 out ----------------
// block: 256 thr (8 warps, 4m x 2n), tile 128 rows x 64 cols. k=64 in 8 steps of 8.
// C = Ah*Wh + Ah*Wl + Al*Wh  (tf32 split; lo*lo dropped)
#define GSTRIDE 68
#define GEMM_SMEM_BYTES ((128 * GSTRIDE + 2 * 64 * GSTRIDE) * 4)

__device__ __forceinline__ unsigned f2tf32(float a) {
    unsigned r;
    asm("cvt.rna.tf32.f32 %0, %1;" : "=r"(r) : "f"(a));
    return r;
}

__device__ __forceinline__ void mma_tf32(float* c, unsigned a0, unsigned a1,
                                         unsigned a2, unsigned a3,
                                         unsigned b0, unsigned b1) {
    asm volatile(
        "mma.sync.aligned.m16n8k8.row.col.f32.tf32.tf32.f32 "
        "{%0,%1,%2,%3}, {%4,%5,%6,%7}, {%8,%9}, {%0,%1,%2,%3};"
        : "+f"(c[0]), "+f"(c[1]), "+f"(c[2]), "+f"(c[3])
        : "r"(a0), "r"(a1), "r"(a2), "r"(a3), "r"(b0), "r"(b1));
}

__global__ __launch_bounds__(256) void gemm_mma_kernel(const float* __restrict__ Ain,
                                                       const float* __restrict__ W,
                                                       int use_hbuf) {
    extern __shared__ float smem[];
    float* sA  = smem;                       // [128][GSTRIDE] fp32
    float* sWh = smem + 128 * GSTRIDE;       // [n][GSTRIDE] (transposed W, tf32-hi)
    float* sWl = sWh + 64 * GSTRIDE;         // [n][GSTRIDE] (tf32-lo)
    const float* A = use_hbuf ? g_hbuf : Ain;

    int t = threadIdx.x;
    int row0 = blockIdx.x * 128;

    for (int e = t; e < 4096; e += 256) {
        int k = e >> 6, n = e & 63;
        float w = W[e];
        unsigned hi = f2tf32(w);
        float lof = w - __uint_as_float(hi);
        sWh[n * GSTRIDE + k] = __uint_as_float(hi);
        sWl[n * GSTRIDE + k] = __uint_as_float(f2tf32(lof));
    }
#pragma unroll
    for (int i = 0; i < 8; i++) {
        int q = t + i * 256;
        int r = q >> 4;
        int c4 = (q & 15) << 2;
        float4 v = make_float4(0.f, 0.f, 0.f, 0.f);
        int grow = row0 + r;
        if (grow < NN) v = *(const float4*)(A + (size_t)grow * 64 + c4);
        *(float4*)(sA + r * GSTRIDE + c4) = v;
    }
    __syncthreads();

    int w8 = t >> 5;
    int mw = w8 >> 1, nw = w8 & 1;
    int mo = mw * 32, no = nw * 32;
    int lane = t & 31;
    int g = lane >> 2, tg = lane & 3;

    float acc[2][4][4];
#pragma unroll
    for (int i = 0; i < 2; i++)
#pragma unroll
        for (int j = 0; j < 4; j++)
#pragma unroll
            for (int c = 0; c < 4; c++) acc[i][j][c] = 0.f;

#pragma unroll
    for (int ks = 0; ks < 8; ks++) {
        int k0 = ks * 8;
        unsigned ah[2][4], al[2][4];
#pragma unroll
        for (int i = 0; i < 2; i++) {
            int r0 = (mo + 16 * i + g) * GSTRIDE;
            int r1 = r0 + 8 * GSTRIDE;
            float a0 = sA[r0 + k0 + tg];
            float a1 = sA[r1 + k0 + tg];
            float a2 = sA[r0 + k0 + tg + 4];
            float a3 = sA[r1 + k0 + tg + 4];
            ah[i][0] = f2tf32(a0); al[i][0] = f2tf32(a0 - __uint_as_float(ah[i][0]));
            ah[i][1] = f2tf32(a1); al[i][1] = f2tf32(a1 - __uint_as_float(ah[i][1]));
            ah[i][2] = f2tf32(a2); al[i][2] = f2tf32(a2 - __uint_as_float(ah[i][2]));
            ah[i][3] = f2tf32(a3); al[i][3] = f2tf32(a3 - __uint_as_float(ah[i][3]));
        }
#pragma unroll
        for (int j = 0; j < 4; j++) {
            int cbase = (no + 8 * j + g) * GSTRIDE + k0 + tg;
            unsigned bh0 = __float_as_uint(sWh[cbase]);
            unsigned bh1 = __float_as_uint(sWh[cbase + 4]);
            unsigned bl0 = __float_as_uint(sWl[cbase]);
            unsigned bl1 = __float_as_uint(sWl[cbase + 4]);
#pragma unroll
            for (int i = 0; i < 2; i++) {
                mma_tf32(acc[i][j], ah[i][0], ah[i][1], ah[i][2], ah[i][3], bh0, bh1);
                mma_tf32(acc[i][j], ah[i][0], ah[i][1], ah[i][2], ah[i][3], bl0, bl1);
                mma_tf32(acc[i][j], al[i][0], al[i][1], al[i][2], al[i][3], bh0, bh1);
            }
        }
    }

    // epilogue: scale by dsinv[row], convert to half2, write g_feat
    __half2* Fv = (__half2*)g_feat;
#pragma unroll
    for (int i = 0; i < 2; i++) {
        int r0 = row0 + mo + 16 * i + g;
        int r1 = r0 + 8;
        float s0 = (r0 < NN) ? g_dsinv[r0] : 0.f;
        float s1 = (r1 < NN) ? g_dsinv[r1] : 0.f;
#pragma unroll
        for (int j = 0; j < 4; j++) {
            int colh = (no + 8 * j + 2 * tg) >> 1;      // half2 slot (pair-aligned)
            if (r0 < NN)
                Fv[r0 * 32 + colh] =
                    __floats2half2_rn(acc[i][j][0] * s0, acc[i][j][1] * s0);
            if (r1 < NN)
                Fv[r1 * 32 + colh] =
                    __floats2half2_rn(acc[i][j][2] * s1, acc[i][j][3] * s1);
        }
    }
}

// ---------------- aggregation: one warp per node, half2 CSR gather, 8-deep MLP ----------------
__global__ __launch_bounds__(256) void aggregate_kernel(const float* __restrict__ bias,
                                                        float* __restrict__ dout,
                                                        int mode) {
    int warp = (blockIdx.x * blockDim.x + threadIdx.x) >> 5;
    int lane = threadIdx.x & 31;
    if (warp >= NN) return;
    int node = warp;
    int beg = g_rowptr[node];
    int end = g_rowptr[node + 1];

    const __half2* __restrict__ Gv = (const __half2*)g_feat;
    int off = node * 32 + lane;
    float2 selfv = __half22float2(Gv[off]);       // self-loop term g[node]
    float ax = selfv.x, ay = selfv.y;

    const unsigned full = 0xffffffffu;
    for (int base = beg; base < end; base += 32) {
        int idx = base + lane;
        int mysrc = (idx < end) ? g_esrc[idx] : 0;
        int cnt = min(32, end - base);
        int i = 0;
        for (; i + 8 <= cnt; i += 8) {
            int s0 = __shfl_sync(full, mysrc, i);
            int s1 = __shfl_sync(full, mysrc, i + 1);
            int s2 = __shfl_sync(full, mysrc, i + 2);
            int s3 = __shfl_sync(full, mysrc, i + 3);
            int s4 = __shfl_sync(full, mysrc, i + 4);
            int s5 = __shfl_sync(full, mysrc, i + 5);
            int s6 = __shfl_sync(full, mysrc, i + 6);
            int s7 = __shfl_sync(full, mysrc, i + 7);
            float2 v0 = __half22float2(Gv[s0 * 32 + lane]);
            float2 v1 = __half22float2(Gv[s1 * 32 + lane]);
            float2 v2 = __half22float2(Gv[s2 * 32 + lane]);
            float2 v3 = __half22float2(Gv[s3 * 32 + lane]);
            float2 v4 = __half22float2(Gv[s4 * 32 + lane]);
            float2 v5 = __half22float2(Gv[s5 * 32 + lane]);
            float2 v6 = __half22float2(Gv[s6 * 32 + lane]);
            float2 v7 = __half22float2(Gv[s7 * 32 + lane]);
            ax += v0.x; ay += v0.y; ax += v1.x; ay += v1.y;
            ax += v2.x; ay += v2.y; ax += v3.x; ay += v3.y;
            ax += v4.x; ay += v4.y; ax += v5.x; ay += v5.y;
            ax += v6.x; ay += v6.y; ax += v7.x; ay += v7.y;
        }
        for (; i < cnt; i++) {
            int s = __shfl_sync(full, mysrc, i);
            float2 v = __half22float2(Gv[s * 32 + lane]);
            ax += v.x; ay += v.y;
        }
    }

    float ds = g_dsinv[node];
    float o0 = fmaf(ds, ax, bias[lane * 2]);
    float o1 = fmaf(ds, ay, bias[lane * 2 + 1]);
    float2* outv;
    if (mode < 2) {
        o0 = fmaxf(o0, 0.f);
        o1 = fmaxf(o1, 0.f);
        outv = (float2*)g_hbuf;
    } else {
        outv = (float2*)dout;
    }
    outv[off] = make_float2(o0, o1);
}

// ---------------- launch ----------------
extern "C" void kernel_launch(void* const* d_in, const int* in_sizes, int n_in,
                              void* d_out, int out_size) {
    const float* x  = (const float*)d_in[0];
    const void*  ei = d_in[1];
    const float* W0 = (const float*)d_in[2];
    const float* b0 = (const float*)d_in[3];
    const float* W1 = (const float*)d_in[4];
    const float* b1 = (const float*)d_in[5];
    const float* W2 = (const float*)d_in[6];
    const float* b2 = (const float*)d_in[7];
    float* out = (float*)d_out;

    int E = in_sizes[1] / 2;

    static int smem_set = 0;
    if (!smem_set) {
        cudaFuncSetAttribute(gemm_mma_kernel,
                             cudaFuncAttributeMaxDynamicSharedMemorySize,
                             GEMM_SMEM_BYTES);
        smem_set = 1;
    }

    hist_kernel<<<(E + 255) / 256, 256>>>(ei, E);
    scan_kernel<<<NB, 256>>>();
    scatter_kernel<<<(E + 255) / 256, 256>>>(ei, E);

    int gemm_blocks = (NN + 127) / 128;
    int agg_blocks  = (NN * 32 + 255) / 256;

    gemm_mma_kernel<<<gemm_blocks, 256, GEMM_SMEM_BYTES>>>(x, W0, 0);
    aggregate_kernel<<<agg_blocks, 256>>>(b0, out, 0);       // launch #5
    gemm_mma_kernel<<<gemm_blocks, 256, GEMM_SMEM_BYTES>>>(x, W1, 1);
    aggregate_kernel<<<agg_blocks, 256>>>(b1, out, 1);
    gemm_mma_kernel<<<gemm_blocks, 256, GEMM_SMEM_BYTES>>>(x, W2, 1);
    aggregate_kernel<<<agg_blocks, 256>>>(b2, out, 2);
}

// round 12
// speedup vs baseline: 1.8417x; 1.1393x over previous
#include <cuda_runtime.h>
#include <cuda_fp16.h>
#include <cstdint>

#define NN   50000
#define MAXE 800000
#define NB   196            // ceil(NN/256)

// ---------------- scratch (static device globals; no allocation) ----------------
__device__ int      g_deg[NN];          // zero-initialized at load; re-zeroed by scan each call
__device__ int      g_rowptr[NN + 1];
__device__ int      g_cursor[NN];
__device__ int      g_esrc[MAXE];
__device__ unsigned g_bstate[NB];       // lookback state: [31:30]=flag (1=agg,2=prefix), [29:0]=sum
__device__ float    g_dsinv[NN];
__device__ __half   g_feat[NN * 64];    // g = (h @ W) * dsinv[row]  (fp16)
__device__ __half   g_hbuf[NN * 64];    // layer output ping buffer  (fp16)

// per-block dtype consensus: read first 256 int64 slots (in-bounds for BOTH layouts)
__device__ __forceinline__ int block_detect_i64(const void* ei) {
    long long v = ((const long long*)ei)[threadIdx.x & 255];
    return __syncthreads_and(v >= 0 && v < NN);
}

// ---------------- hist: deg histogram (+ lookback-state reset by block 0) ----------------
__global__ __launch_bounds__(256) void hist_kernel(const void* __restrict__ ei, int E) {
    int is64 = block_detect_i64(ei);
    if (blockIdx.x == 0 && threadIdx.x < NB) g_bstate[threadIdx.x] = 0u;
    int e = blockIdx.x * 256 + threadIdx.x;
    if (e < E) {
        int d = is64 ? (int)((const long long*)ei)[(long long)E + e]
                     : ((const int*)ei)[(long long)E + e];
        if ((unsigned)d < (unsigned)NN) atomicAdd(&g_deg[d], 1);
    }
}

// ---------------- single-kernel decoupled-lookback scan ----------------
__global__ __launch_bounds__(256) void scan_kernel() {
    const unsigned full = 0xffffffffu;
    __shared__ int sh[8];
    __shared__ int s_prefix;
    int b = blockIdx.x, t = threadIdx.x;
    int lane = t & 31, wid = t >> 5;
    int i = b * 256 + t;

    int v = (i < NN) ? g_deg[i] : 0;

    int x = v;
#pragma unroll
    for (int d = 1; d < 32; d <<= 1) {
        int n = __shfl_up_sync(full, x, d);
        if (lane >= d) x += n;
    }
    if (lane == 31) sh[wid] = x;
    __syncthreads();
    if (wid == 0) {
        int w = (lane < 8) ? sh[lane] : 0;
#pragma unroll
        for (int d = 1; d < 8; d <<= 1) {
            int n = __shfl_up_sync(full, w, d);
            if (lane >= d) w += n;
        }
        if (lane < 8) sh[lane] = w;
    }
    __syncthreads();
    int incl = x + (wid ? sh[wid - 1] : 0);
    int S = sh[7];

    if (t == 0 && b > 0) atomicExch((int*)&g_bstate[b], (1 << 30) | S);

    if (wid == 0) {
        int running = 0;
        if (b > 0) {
            int idx = b - 1;
            while (true) {
                int j = idx - lane;
                unsigned st;
                do {
                    st = (j >= 0) ? (unsigned)atomicAdd((int*)&g_bstate[j], 0)
                                  : (2u << 30);
                } while (__any_sync(full, (st >> 30) == 0));
                int val = (int)(st & 0x3FFFFFFF);
                unsigned pm = __ballot_sync(full, (st >> 30) == 2u);
                if (pm) {
                    int firstP = __ffs(pm) - 1;
                    int contrib = (lane <= firstP) ? val : 0;
#pragma unroll
                    for (int d = 16; d; d >>= 1) contrib += __shfl_down_sync(full, contrib, d);
                    running += __shfl_sync(full, contrib, 0);
                    break;
                } else {
                    int contrib = val;
#pragma unroll
                    for (int d = 16; d; d >>= 1) contrib += __shfl_down_sync(full, contrib, d);
                    running += __shfl_sync(full, contrib, 0);
                    idx -= 32;
                }
            }
        }
        if (lane == 0) {
            atomicExch((int*)&g_bstate[b], (2 << 30) | (running + S));
            s_prefix = running;
        }
    }
    __syncthreads();

    if (i < NN) {
        int excl = s_prefix + incl - v;
        g_rowptr[i] = excl;
        g_cursor[i] = excl;
        g_dsinv[i]  = rsqrtf((float)(v + 1));
        g_deg[i]    = 0;
        if (i == NN - 1) g_rowptr[NN] = s_prefix + incl;
    }
}

// ---------------- scatter: fill CSR adjacency ----------------
__global__ __launch_bounds__(256) void scatter_kernel(const void* __restrict__ ei, int E) {
    int is64 = block_detect_i64(ei);
    int e = blockIdx.x * 256 + threadIdx.x;
    if (e < E) {
        int s, d;
        if (is64) {
            s = (int)((const long long*)ei)[e];
            d = (int)((const long long*)ei)[(long long)E + e];
        } else {
            s = ((const int*)ei)[e];
            d = ((const int*)ei)[(long long)E + e];
        }
        if ((unsigned)d < (unsigned)NN && (unsigned)s < (unsigned)NN) {
            int p = atomicAdd(&g_cursor[d], 1);
            if ((unsigned)p < (unsigned)MAXE) g_esrc[p] = s;
        }
    }
}

// ---------------- fp16 tensor-core GEMM: g = (A @ W) * dsinv[row] ----------------
// block: 256 thr (8 warps, 4m x 2n), tile 128 rows x 64 cols, k=64 in 4 steps of 16.
// A, W converted to fp16; fp32 accumulate via mma.m16n8k16.
#define AST 72                            // half stride for sA rows (bank-conflict-free)
#define GEMM_SMEM_BYTES ((128 * AST + 64 * AST) * 2)

__device__ __forceinline__ void mma_f16(float* c, unsigned a0, unsigned a1,
                                        unsigned a2, unsigned a3,
                                        unsigned b0, unsigned b1) {
    asm volatile(
        "mma.sync.aligned.m16n8k16.row.col.f32.f16.f16.f32 "
        "{%0,%1,%2,%3}, {%4,%5,%6,%7}, {%8,%9}, {%0,%1,%2,%3};"
        : "+f"(c[0]), "+f"(c[1]), "+f"(c[2]), "+f"(c[3])
        : "r"(a0), "r"(a1), "r"(a2), "r"(a3), "r"(b0), "r"(b1));
}

__global__ __launch_bounds__(256) void gemm_mma_kernel(const float* __restrict__ Ain,
                                                       const float* __restrict__ W,
                                                       int use_hbuf) {
    extern __shared__ __half smem[];
    __half* sA  = smem;                    // [128][AST] half
    __half* sWT = smem + 128 * AST;        // [n][AST] half  (W transposed)

    int t = threadIdx.x;
    int row0 = blockIdx.x * 128;

    // W^T -> smem fp16 (4096 scalar stores; tiny)
    for (int e = t; e < 4096; e += 256) {
        int k = e >> 6, n = e & 63;        // W row-major [k][n]
        sWT[n * AST + k] = __float2half_rn(W[e]);
    }

    // A tile -> smem fp16
    if (!use_hbuf) {
#pragma unroll
        for (int i = 0; i < 8; i++) {
            int q = t + i * 256;           // float4 index 0..2047
            int r = q >> 4;
            int c4 = (q & 15) << 2;
            float4 v = make_float4(0.f, 0.f, 0.f, 0.f);
            int grow = row0 + r;
            if (grow < NN) v = *(const float4*)(Ain + (size_t)grow * 64 + c4);
            __half2* dst = (__half2*)(sA + r * AST + c4);
            dst[0] = __floats2half2_rn(v.x, v.y);
            dst[1] = __floats2half2_rn(v.z, v.w);
        }
    } else {
#pragma unroll
        for (int i = 0; i < 4; i++) {
            int q = t + i * 256;           // 8-half chunk index 0..1023
            int r = q >> 3;
            int c8 = (q & 7) << 3;
            float4 v = make_float4(0.f, 0.f, 0.f, 0.f);
            int grow = row0 + r;
            if (grow < NN) v = *(const float4*)(g_hbuf + (size_t)grow * 64 + c8);
            *(float4*)(sA + r * AST + c8) = v;
        }
    }
    __syncthreads();

    int w8 = t >> 5;
    int mw = w8 >> 1, nw = w8 & 1;        // 4m x 2n warps
    int mo = mw * 32, no = nw * 32;
    int lane = t & 31;
    int g = lane >> 2, tg = lane & 3;

    float acc[2][4][4];
#pragma unroll
    for (int i = 0; i < 2; i++)
#pragma unroll
        for (int j = 0; j < 4; j++)
#pragma unroll
            for (int c = 0; c < 4; c++) acc[i][j][c] = 0.f;

#pragma unroll
    for (int ks = 0; ks < 4; ks++) {
        int k0 = ks * 16;
        unsigned a[2][4];
#pragma unroll
        for (int i = 0; i < 2; i++) {
            const __half* r0p = sA + (mo + 16 * i + g) * AST + k0 + tg * 2;
            const __half* r1p = r0p + 8 * AST;
            a[i][0] = *(const unsigned*)r0p;
            a[i][1] = *(const unsigned*)r1p;
            a[i][2] = *(const unsigned*)(r0p + 8);
            a[i][3] = *(const unsigned*)(r1p + 8);
        }
#pragma unroll
        for (int j = 0; j < 4; j++) {
            const __half* bp = sWT + (no + 8 * j + g) * AST + k0 + tg * 2;
            unsigned b0 = *(const unsigned*)bp;
            unsigned b1 = *(const unsigned*)(bp + 8);
#pragma unroll
            for (int i = 0; i < 2; i++)
                mma_f16(acc[i][j], a[i][0], a[i][1], a[i][2], a[i][3], b0, b1);
        }
    }

    // epilogue: scale by dsinv[row], convert to half2, write g_feat
    __half2* Fv = (__half2*)g_feat;
#pragma unroll
    for (int i = 0; i < 2; i++) {
        int r0 = row0 + mo + 16 * i + g;
        int r1 = r0 + 8;
        float s0 = (r0 < NN) ? g_dsinv[r0] : 0.f;
        float s1 = (r1 < NN) ? g_dsinv[r1] : 0.f;
#pragma unroll
        for (int j = 0; j < 4; j++) {
            int colh = (no + 8 * j + 2 * tg) >> 1;
            if (r0 < NN)
                Fv[r0 * 32 + colh] =
                    __floats2half2_rn(acc[i][j][0] * s0, acc[i][j][1] * s0);
            if (r1 < NN)
                Fv[r1 * 32 + colh] =
                    __floats2half2_rn(acc[i][j][2] * s1, acc[i][j][3] * s1);
        }
    }
}

// ---------------- aggregation: one warp per node, half2 CSR gather, 8-deep MLP ----------------
__global__ __launch_bounds__(256) void aggregate_kernel(const float* __restrict__ bias,
                                                        float* __restrict__ dout,
                                                        int mode) {
    int warp = (blockIdx.x * blockDim.x + threadIdx.x) >> 5;
    int lane = threadIdx.x & 31;
    if (warp >= NN) return;
    int node = warp;
    int beg = g_rowptr[node];
    int end = g_rowptr[node + 1];

    const __half2* __restrict__ Gv = (const __half2*)g_feat;
    int off = node * 32 + lane;
    float2 selfv = __half22float2(Gv[off]);       // self-loop term g[node]
    float ax = selfv.x, ay = selfv.y;

    const unsigned full = 0xffffffffu;
    for (int base = beg; base < end; base += 32) {
        int idx = base + lane;
        int mysrc = (idx < end) ? g_esrc[idx] : 0;
        int cnt = min(32, end - base);
        int i = 0;
        for (; i + 8 <= cnt; i += 8) {
            int s0 = __shfl_sync(full, mysrc, i);
            int s1 = __shfl_sync(full, mysrc, i + 1);
            int s2 = __shfl_sync(full, mysrc, i + 2);
            int s3 = __shfl_sync(full, mysrc, i + 3);
            int s4 = __shfl_sync(full, mysrc, i + 4);
            int s5 = __shfl_sync(full, mysrc, i + 5);
            int s6 = __shfl_sync(full, mysrc, i + 6);
            int s7 = __shfl_sync(full, mysrc, i + 7);
            float2 v0 = __half22float2(Gv[s0 * 32 + lane]);
            float2 v1 = __half22float2(Gv[s1 * 32 + lane]);
            float2 v2 = __half22float2(Gv[s2 * 32 + lane]);
            float2 v3 = __half22float2(Gv[s3 * 32 + lane]);
            float2 v4 = __half22float2(Gv[s4 * 32 + lane]);
            float2 v5 = __half22float2(Gv[s5 * 32 + lane]);
            float2 v6 = __half22float2(Gv[s6 * 32 + lane]);
            float2 v7 = __half22float2(Gv[s7 * 32 + lane]);
            ax += v0.x; ay += v0.y; ax += v1.x; ay += v1.y;
            ax += v2.x; ay += v2.y; ax += v3.x; ay += v3.y;
            ax += v4.x; ay += v4.y; ax += v5.x; ay += v5.y;
            ax += v6.x; ay += v6.y; ax += v7.x; ay += v7.y;
        }
        for (; i < cnt; i++) {
            int s = __shfl_sync(full, mysrc, i);
            float2 v = __half22float2(Gv[s * 32 + lane]);
            ax += v.x; ay += v.y;
        }
    }

    float ds = g_dsinv[node];
    float o0 = fmaf(ds, ax, bias[lane * 2]);
    float o1 = fmaf(ds, ay, bias[lane * 2 + 1]);
    if (mode < 2) {
        o0 = fmaxf(o0, 0.f);
        o1 = fmaxf(o1, 0.f);
        ((__half2*)g_hbuf)[off] = __floats2half2_rn(o0, o1);
    } else {
        ((float2*)dout)[off] = make_float2(o0, o1);
    }
}

// ---------------- launch ----------------
extern "C" void kernel_launch(void* const* d_in, const int* in_sizes, int n_in,
                              void* d_out, int out_size) {
    const float* x  = (const float*)d_in[0];
    const void*  ei = d_in[1];
    const float* W0 = (const float*)d_in[2];
    const float* b0 = (const float*)d_in[3];
    const float* W1 = (const float*)d_in[4];
    const float* b1 = (const float*)d_in[5];
    const float* W2 = (const float*)d_in[6];
    const float* b2 = (const float*)d_in[7];
    float* out = (float*)d_out;

    int E = in_sizes[1] / 2;

    hist_kernel<<<(E + 255) / 256, 256>>>(ei, E);
    scan_kernel<<<NB, 256>>>();
    scatter_kernel<<<(E + 255) / 256, 256>>>(ei, E);

    int gemm_blocks = (NN + 127) / 128;
    int agg_blocks  = (NN * 32 + 255) / 256;

    gemm_mma_kernel<<<gemm_blocks, 256, GEMM_SMEM_BYTES>>>(x, W0, 0);   // launch #4 -> profiled
    aggregate_kernel<<<agg_blocks, 256>>>(b0, out, 0);
    gemm_mma_kernel<<<gemm_blocks, 256, GEMM_SMEM_BYTES>>>(x, W1, 1);
    aggregate_kernel<<<agg_blocks, 256>>>(b1, out, 1);
    gemm_mma_kernel<<<gemm_blocks, 256, GEMM_SMEM_BYTES>>>(x, W2, 1);
    aggregate_kernel<<<agg_blocks, 256>>>(b2, out, 2);
}

// round 13
// speedup vs baseline: 1.8486x; 1.0037x over previous
#include <cuda_runtime.h>
#include <cuda_fp16.h>
#include <cstdint>

#define NN   50000
#define MAXE 800000
#define NB   196            // ceil(NN/256)
#define AST  72             // half stride (bank-conflict-free, 16B-aligned rows)

// ---------------- scratch (static device globals; no allocation) ----------------
__device__ int      g_deg[NN];          // zero-initialized at load; re-zeroed by scan each call
__device__ int      g_rowptr[NN + 1];
__device__ int      g_cursor[NN];
__device__ int      g_esrc[MAXE];
__device__ unsigned g_bstate[NB];       // lookback state: [31:30]=flag (1=agg,2=prefix), [29:0]=sum
__device__ float    g_dsinv[NN];
__device__ __half   g_feat[NN * 64];    // g = (h @ W) * dsinv[row]  (fp16)
__device__ __half   g_hbuf[NN * 64];    // layer output ping buffer  (fp16)
__device__ __half   g_Wt[3 * 64 * AST]; // per-layer W^T fp16, [n][k] stride AST

// per-block dtype consensus: read first 256 int64 slots (in-bounds for BOTH layouts)
__device__ __forceinline__ int block_detect_i64(const void* ei) {
    long long v = ((const long long*)ei)[threadIdx.x & 255];
    return __syncthreads_and(v >= 0 && v < NN);
}

// ---------------- W^T fp16 precompute: 3 blocks, one per layer ----------------
__global__ __launch_bounds__(256) void wsplit_kernel(const float* __restrict__ W0,
                                                     const float* __restrict__ W1,
                                                     const float* __restrict__ W2) {
    const float* W = (blockIdx.x == 0) ? W0 : (blockIdx.x == 1) ? W1 : W2;
    __half* dst = g_Wt + blockIdx.x * 64 * AST;
    for (int e = threadIdx.x; e < 4096; e += 256) {
        int k = e >> 6, n = e & 63;        // W row-major [k][n]
        dst[n * AST + k] = __float2half_rn(W[e]);
    }
}

// ---------------- hist: deg histogram (+ lookback-state reset by block 0) ----------------
__global__ __launch_bounds__(256) void hist_kernel(const void* __restrict__ ei, int E) {
    int is64 = block_detect_i64(ei);
    if (blockIdx.x == 0 && threadIdx.x < NB) g_bstate[threadIdx.x] = 0u;
    int e = blockIdx.x * 256 + threadIdx.x;
    if (e < E) {
        int d = is64 ? (int)((const long long*)ei)[(long long)E + e]
                     : ((const int*)ei)[(long long)E + e];
        if ((unsigned)d < (unsigned)NN) atomicAdd(&g_deg[d], 1);
    }
}

// ---------------- single-kernel decoupled-lookback scan ----------------
__global__ __launch_bounds__(256) void scan_kernel() {
    const unsigned full = 0xffffffffu;
    __shared__ int sh[8];
    __shared__ int s_prefix;
    int b = blockIdx.x, t = threadIdx.x;
    int lane = t & 31, wid = t >> 5;
    int i = b * 256 + t;

    int v = (i < NN) ? g_deg[i] : 0;

    int x = v;
#pragma unroll
    for (int d = 1; d < 32; d <<= 1) {
        int n = __shfl_up_sync(full, x, d);
        if (lane >= d) x += n;
    }
    if (lane == 31) sh[wid] = x;
    __syncthreads();
    if (wid == 0) {
        int w = (lane < 8) ? sh[lane] : 0;
#pragma unroll
        for (int d = 1; d < 8; d <<= 1) {
            int n = __shfl_up_sync(full, w, d);
            if (lane >= d) w += n;
        }
        if (lane < 8) sh[lane] = w;
    }
    __syncthreads();
    int incl = x + (wid ? sh[wid - 1] : 0);
    int S = sh[7];

    if (t == 0 && b > 0) atomicExch((int*)&g_bstate[b], (1 << 30) | S);

    if (wid == 0) {
        int running = 0;
        if (b > 0) {
            int idx = b - 1;
            while (true) {
                int j = idx - lane;
                unsigned st;
                do {
                    st = (j >= 0) ? (unsigned)atomicAdd((int*)&g_bstate[j], 0)
                                  : (2u << 30);
                } while (__any_sync(full, (st >> 30) == 0));
                int val = (int)(st & 0x3FFFFFFF);
                unsigned pm = __ballot_sync(full, (st >> 30) == 2u);
                if (pm) {
                    int firstP = __ffs(pm) - 1;
                    int contrib = (lane <= firstP) ? val : 0;
#pragma unroll
                    for (int d = 16; d; d >>= 1) contrib += __shfl_down_sync(full, contrib, d);
                    running += __shfl_sync(full, contrib, 0);
                    break;
                } else {
                    int contrib = val;
#pragma unroll
                    for (int d = 16; d; d >>= 1) contrib += __shfl_down_sync(full, contrib, d);
                    running += __shfl_sync(full, contrib, 0);
                    idx -= 32;
                }
            }
        }
        if (lane == 0) {
            atomicExch((int*)&g_bstate[b], (2 << 30) | (running + S));
            s_prefix = running;
        }
    }
    __syncthreads();

    if (i < NN) {
        int excl = s_prefix + incl - v;
        g_rowptr[i] = excl;
        g_cursor[i] = excl;
        g_dsinv[i]  = rsqrtf((float)(v + 1));
        g_deg[i]    = 0;
        if (i == NN - 1) g_rowptr[NN] = s_prefix + incl;
    }
}

// ---------------- scatter: fill CSR adjacency ----------------
__global__ __launch_bounds__(256) void scatter_kernel(const void* __restrict__ ei, int E) {
    int is64 = block_detect_i64(ei);
    int e = blockIdx.x * 256 + threadIdx.x;
    if (e < E) {
        int s, d;
        if (is64) {
            s = (int)((const long long*)ei)[e];
            d = (int)((const long long*)ei)[(long long)E + e];
        } else {
            s = ((const int*)ei)[e];
            d = ((const int*)ei)[(long long)E + e];
        }
        if ((unsigned)d < (unsigned)NN && (unsigned)s < (unsigned)NN) {
            int p = atomicAdd(&g_cursor[d], 1);
            if ((unsigned)p < (unsigned)MAXE) g_esrc[p] = s;
        }
    }
}

// ---------------- fp16 tensor-core GEMM: g = (A @ W) * dsinv[row] ----------------
// block: 256 thr (8 warps, 4m x 2n), tile 128 rows x 64 cols, k=64 in 4 steps of 16.
// W^T precomputed fp16 (g_Wt) -> float4 smem copy. fp32 accumulate via mma.m16n8k16.
#define GEMM_SMEM_BYTES ((128 * AST + 64 * AST) * 2)

__device__ __forceinline__ void mma_f16(float* c, unsigned a0, unsigned a1,
                                        unsigned a2, unsigned a3,
                                        unsigned b0, unsigned b1) {
    asm volatile(
        "mma.sync.aligned.m16n8k16.row.col.f32.f16.f16.f32 "
        "{%0,%1,%2,%3}, {%4,%5,%6,%7}, {%8,%9}, {%0,%1,%2,%3};"
        : "+f"(c[0]), "+f"(c[1]), "+f"(c[2]), "+f"(c[3])
        : "r"(a0), "r"(a1), "r"(a2), "r"(a3), "r"(b0), "r"(b1));
}

__global__ __launch_bounds__(256) void gemm_mma_kernel(const float* __restrict__ Ain,
                                                       int layer, int use_hbuf) {
    extern __shared__ __half smem[];
    __half* sA  = smem;                    // [128][AST] half
    __half* sWT = smem + 128 * AST;        // [n][AST] half  (W transposed)

    int t = threadIdx.x;
    int row0 = blockIdx.x * 128;

    // W^T smem copy: 64*AST halves = 576 float4
    {
        const float4* src = (const float4*)(g_Wt + layer * 64 * AST);
        float4* dst = (float4*)sWT;
        for (int i = t; i < (64 * AST) / 8; i += 256) dst[i] = src[i];
    }

    // A tile -> smem fp16
    if (!use_hbuf) {
#pragma unroll
        for (int i = 0; i < 8; i++) {
            int q = t + i * 256;           // float4 index 0..2047
            int r = q >> 4;
            int c4 = (q & 15) << 2;
            float4 v = make_float4(0.f, 0.f, 0.f, 0.f);
            int grow = row0 + r;
            if (grow < NN) v = *(const float4*)(Ain + (size_t)grow * 64 + c4);
            __half2* dst = (__half2*)(sA + r * AST + c4);
            dst[0] = __floats2half2_rn(v.x, v.y);
            dst[1] = __floats2half2_rn(v.z, v.w);
        }
    } else {
#pragma unroll
        for (int i = 0; i < 4; i++) {
            int q = t + i * 256;           // 8-half chunk index 0..1023
            int r = q >> 3;
            int c8 = (q & 7) << 3;
            float4 v = make_float4(0.f, 0.f, 0.f, 0.f);
            int grow = row0 + r;
            if (grow < NN) v = *(const float4*)(g_hbuf + (size_t)grow * 64 + c8);
            *(float4*)(sA + r * AST + c8) = v;
        }
    }
    __syncthreads();

    int w8 = t >> 5;
    int mw = w8 >> 1, nw = w8 & 1;        // 4m x 2n warps
    int mo = mw * 32, no = nw * 32;
    int lane = t & 31;
    int g = lane >> 2, tg = lane & 3;

    float acc[2][4][4];
#pragma unroll
    for (int i = 0; i < 2; i++)
#pragma unroll
        for (int j = 0; j < 4; j++)
#pragma unroll
            for (int c = 0; c < 4; c++) acc[i][j][c] = 0.f;

#pragma unroll
    for (int ks = 0; ks < 4; ks++) {
        int k0 = ks * 16;
        unsigned a[2][4];
#pragma unroll
        for (int i = 0; i < 2; i++) {
            const __half* r0p = sA + (mo + 16 * i + g) * AST + k0 + tg * 2;
            const __half* r1p = r0p + 8 * AST;
            a[i][0] = *(const unsigned*)r0p;
            a[i][1] = *(const unsigned*)r1p;
            a[i][2] = *(const unsigned*)(r0p + 8);
            a[i][3] = *(const unsigned*)(r1p + 8);
        }
#pragma unroll
        for (int j = 0; j < 4; j++) {
            const __half* bp = sWT + (no + 8 * j + g) * AST + k0 + tg * 2;
            unsigned b0 = *(const unsigned*)bp;
            unsigned b1 = *(const unsigned*)(bp + 8);
#pragma unroll
            for (int i = 0; i < 2; i++)
                mma_f16(acc[i][j], a[i][0], a[i][1], a[i][2], a[i][3], b0, b1);
        }
    }

    // epilogue: scale by dsinv[row], convert to half2, write g_feat
    __half2* Fv = (__half2*)g_feat;
#pragma unroll
    for (int i = 0; i < 2; i++) {
        int r0 = row0 + mo + 16 * i + g;
        int r1 = r0 + 8;
        float s0 = (r0 < NN) ? g_dsinv[r0] : 0.f;
        float s1 = (r1 < NN) ? g_dsinv[r1] : 0.f;
#pragma unroll
        for (int j = 0; j < 4; j++) {
            int colh = (no + 8 * j + 2 * tg) >> 1;
            if (r0 < NN)
                Fv[r0 * 32 + colh] =
                    __floats2half2_rn(acc[i][j][0] * s0, acc[i][j][1] * s0);
            if (r1 < NN)
                Fv[r1 * 32 + colh] =
                    __floats2half2_rn(acc[i][j][2] * s1, acc[i][j][3] * s1);
        }
    }
}

// ---------------- aggregation: one warp per node, half2 CSR gather, 8-deep MLP ----------------
__global__ __launch_bounds__(256) void aggregate_kernel(const float* __restrict__ bias,
                                                        float* __restrict__ dout,
                                                        int mode) {
    int warp = (blockIdx.x * blockDim.x + threadIdx.x) >> 5;
    int lane = threadIdx.x & 31;
    if (warp >= NN) return;
    int node = warp;
    int beg = g_rowptr[node];
    int end = g_rowptr[node + 1];

    const __half2* __restrict__ Gv = (const __half2*)g_feat;
    int off = node * 32 + lane;
    float2 selfv = __half22float2(Gv[off]);       // self-loop term g[node]
    float ax = selfv.x, ay = selfv.y;

    const unsigned full = 0xffffffffu;
    for (int base = beg; base < end; base += 32) {
        int idx = base + lane;
        int mysrc = (idx < end) ? g_esrc[idx] : 0;
        int cnt = min(32, end - base);
        int i = 0;
        for (; i + 8 <= cnt; i += 8) {
            int s0 = __shfl_sync(full, mysrc, i);
            int s1 = __shfl_sync(full, mysrc, i + 1);
            int s2 = __shfl_sync(full, mysrc, i + 2);
            int s3 = __shfl_sync(full, mysrc, i + 3);
            int s4 = __shfl_sync(full, mysrc, i + 4);
            int s5 = __shfl_sync(full, mysrc, i + 5);
            int s6 = __shfl_sync(full, mysrc, i + 6);
            int s7 = __shfl_sync(full, mysrc, i + 7);
            float2 v0 = __half22float2(Gv[s0 * 32 + lane]);
            float2 v1 = __half22float2(Gv[s1 * 32 + lane]);
            float2 v2 = __half22float2(Gv[s2 * 32 + lane]);
            float2 v3 = __half22float2(Gv[s3 * 32 + lane]);
            float2 v4 = __half22float2(Gv[s4 * 32 + lane]);
            float2 v5 = __half22float2(Gv[s5 * 32 + lane]);
            float2 v6 = __half22float2(Gv[s6 * 32 + lane]);
            float2 v7 = __half22float2(Gv[s7 * 32 + lane]);
            ax += v0.x; ay += v0.y; ax += v1.x; ay += v1.y;
            ax += v2.x; ay += v2.y; ax += v3.x; ay += v3.y;
            ax += v4.x; ay += v4.y; ax += v5.x; ay += v5.y;
            ax += v6.x; ay += v6.y; ax += v7.x; ay += v7.y;
        }
        for (; i < cnt; i++) {
            int s = __shfl_sync(full, mysrc, i);
            float2 v = __half22float2(Gv[s * 32 + lane]);
            ax += v.x; ay += v.y;
        }
    }

    float ds = g_dsinv[node];
    float o0 = fmaf(ds, ax, bias[lane * 2]);
    float o1 = fmaf(ds, ay, bias[lane * 2 + 1]);
    if (mode < 2) {
        o0 = fmaxf(o0, 0.f);
        o1 = fmaxf(o1, 0.f);
        ((__half2*)g_hbuf)[off] = __floats2half2_rn(o0, o1);
    } else {
        ((float2*)dout)[off] = make_float2(o0, o1);
    }
}

// ---------------- launch ----------------
extern "C" void kernel_launch(void* const* d_in, const int* in_sizes, int n_in,
                              void* d_out, int out_size) {
    const float* x  = (const float*)d_in[0];
    const void*  ei = d_in[1];
    const float* W0 = (const float*)d_in[2];
    const float* b0 = (const float*)d_in[3];
    const float* W1 = (const float*)d_in[4];
    const float* b1 = (const float*)d_in[5];
    const float* W2 = (const float*)d_in[6];
    const float* b2 = (const float*)d_in[7];
    float* out = (float*)d_out;

    int E = in_sizes[1] / 2;

    static int smem_set = 0;
    if (!smem_set) {
        cudaFuncSetAttribute(gemm_mma_kernel,
                             cudaFuncAttributeMaxDynamicSharedMemorySize,
                             GEMM_SMEM_BYTES);
        smem_set = 1;
    }

    int gemm_blocks = (NN + 127) / 128;
    int agg_blocks  = (NN * 32 + 255) / 256;

    wsplit_kernel<<<3, 256>>>(W0, W1, W2);                   // 1
    hist_kernel<<<(E + 255) / 256, 256>>>(ei, E);            // 2
    scan_kernel<<<NB, 256>>>();                              // 3
    gemm_mma_kernel<<<gemm_blocks, 256, GEMM_SMEM_BYTES>>>(x, 0, 0);   // 4 -> profiled
    scatter_kernel<<<(E + 255) / 256, 256>>>(ei, E);         // 5
    aggregate_kernel<<<agg_blocks, 256>>>(b0, out, 0);       // 6
    gemm_mma_kernel<<<gemm_blocks, 256, GEMM_SMEM_BYTES>>>(x, 1, 1);
    aggregate_kernel<<<agg_blocks, 256>>>(b1, out, 1);
    gemm_mma_kernel<<<gemm_blocks, 256, GEMM_SMEM_BYTES>>>(x, 2, 1);
    aggregate_kernel<<<agg_blocks, 256>>>(b2, out, 2);
}